// round 1
// baseline (speedup 1.0000x reference)
#include <cuda_runtime.h>
#include <cuda_bf16.h>
#include <math.h>

// LSTM cell: B=4096, I=1024, H=1024
// ifgo[4096, 4096] = [x | h] @ [W_i ; W_h] + (b_i + b_h)
// i,f,g,o = split(ifgo, 4); c_new = sig(f)*c + sig(i)*tanh(g); h_new = sig(o)*tanh(c_new)
// Output: h_new (4096x1024) followed by c_new (4096x1024), fp32.
//
// Round-0 baseline: fp32 tiled GEMM, fully fused epilogue.
// Block tile: 128 rows (M) x 32 j0-columns x 4 gates (=128 GEMM cols), BK=16.
// 256 threads, 8x8 register micro-tile per thread; thread owns 2 j0-columns
// across all 4 gates so the LSTM epilogue is thread-local.

#define MDIM   4096
#define HDIM   1024
#define KDIM   2048
#define BK     16
#define BM     128
#define BNJ    32          // j0 columns per block (x4 gates = 128 GEMM cols)
#define NTILES (KDIM / BK) // 128

__global__ __launch_bounds__(256, 2)
void lstm_cell_kernel(const float* __restrict__ x,
                      const float* __restrict__ h_t,
                      const float* __restrict__ c_t,
                      const float* __restrict__ w_i,
                      const float* __restrict__ w_h,
                      const float* __restrict__ b_i,
                      const float* __restrict__ b_h,
                      float* __restrict__ out)
{
    __shared__ float As[BK][BM + 4];   // [k][m], padded stride 132 (528B, 16B-aligned rows)
    __shared__ float Bs[BK][128];      // [k][g*32 + jj]

    const int tid = threadIdx.x;
    const int tx  = tid & 15;          // 0..15 -> j0 pair
    const int ty  = tid >> 4;          // 0..15 -> row group
    const int mbase = blockIdx.y * BM;
    const int nbase = blockIdx.x * BNJ;

    float acc[8][8];
    #pragma unroll
    for (int i = 0; i < 8; ++i)
        #pragma unroll
        for (int c = 0; c < 8; ++c) acc[i][c] = 0.0f;

    float4 a_pref[2];
    float4 b_pref[2];

    // ---- global-load helpers (inlined) ----
    auto load_tile = [&](int t) {
        const int kbase = t * BK;
        const float* asrc; const float* wsrc; int koff;
        if (kbase < 1024) { asrc = x;   wsrc = w_i; koff = kbase; }
        else              { asrc = h_t; wsrc = w_h; koff = kbase - 1024; }
        #pragma unroll
        for (int q = 0; q < 2; ++q) {
            int l   = tid + q * 256;       // A: 0..511
            int row = l >> 2;              // 0..127
            int kq  = (l & 3) << 2;        // 0,4,8,12
            a_pref[q] = *reinterpret_cast<const float4*>(
                &asrc[(size_t)(mbase + row) * 1024 + koff + kq]);
        }
        #pragma unroll
        for (int q = 0; q < 2; ++q) {
            int l   = tid + q * 256;       // B: 0..511
            int k   = l >> 5;              // 0..15
            int rem = l & 31;
            int g   = rem >> 3;            // 0..3
            int jjq = (rem & 7) << 2;      // 0..28
            b_pref[q] = *reinterpret_cast<const float4*>(
                &wsrc[(size_t)(koff + k) * 4096 + g * 1024 + nbase + jjq]);
        }
    };

    auto store_tile = [&]() {
        #pragma unroll
        for (int q = 0; q < 2; ++q) {
            int l   = tid + q * 256;
            int row = l >> 2;
            int kq  = (l & 3) << 2;
            As[kq + 0][row] = a_pref[q].x;
            As[kq + 1][row] = a_pref[q].y;
            As[kq + 2][row] = a_pref[q].z;
            As[kq + 3][row] = a_pref[q].w;
        }
        #pragma unroll
        for (int q = 0; q < 2; ++q) {
            int l   = tid + q * 256;
            int k   = l >> 5;
            int rem = l & 31;
            int g   = rem >> 3;
            int jjq = (rem & 7) << 2;
            *reinterpret_cast<float4*>(&Bs[k][g * 32 + jjq]) = b_pref[q];
        }
    };

    // ---- main loop: register-prefetch single-buffer ----
    load_tile(0);
    for (int t = 0; t < NTILES; ++t) {
        store_tile();
        __syncthreads();
        if (t + 1 < NTILES) load_tile(t + 1);

        #pragma unroll
        for (int k = 0; k < BK; ++k) {
            float a[8];
            float4 a0 = *reinterpret_cast<const float4*>(&As[k][ty * 8]);
            float4 a1 = *reinterpret_cast<const float4*>(&As[k][ty * 8 + 4]);
            a[0] = a0.x; a[1] = a0.y; a[2] = a0.z; a[3] = a0.w;
            a[4] = a1.x; a[5] = a1.y; a[6] = a1.z; a[7] = a1.w;

            float b[8];
            #pragma unroll
            for (int g = 0; g < 4; ++g) {
                float2 v = *reinterpret_cast<const float2*>(&Bs[k][g * 32 + tx * 2]);
                b[g * 2 + 0] = v.x;
                b[g * 2 + 1] = v.y;
            }

            #pragma unroll
            for (int i = 0; i < 8; ++i)
                #pragma unroll
                for (int c = 0; c < 8; ++c)
                    acc[i][c] = fmaf(a[i], b[c], acc[i][c]);
        }
        __syncthreads();
    }

    // ---- fused LSTM epilogue ----
    const int row0 = mbase + ty * 8;
    const int col0 = nbase + tx * 2;

    float bias[8];
    #pragma unroll
    for (int g = 0; g < 4; ++g)
        #pragma unroll
        for (int p = 0; p < 2; ++p) {
            int n = g * 1024 + col0 + p;
            bias[g * 2 + p] = b_i[n] + b_h[n];
        }

    float* out_h = out;
    float* out_c = out + (size_t)MDIM * HDIM;

    #pragma unroll
    for (int i = 0; i < 8; ++i) {
        const int row = row0 + i;
        float2 cold = *reinterpret_cast<const float2*>(&c_t[(size_t)row * 1024 + col0]);
        float hn[2], cn[2];
        #pragma unroll
        for (int p = 0; p < 2; ++p) {
            float xi = acc[i][0 + p] + bias[0 + p];
            float xf = acc[i][2 + p] + bias[2 + p];
            float xg = acc[i][4 + p] + bias[4 + p];
            float xo = acc[i][6 + p] + bias[6 + p];
            float iv = 1.0f / (1.0f + expf(-xi));
            float fv = 1.0f / (1.0f + expf(-xf));
            float gv = tanhf(xg);
            float ov = 1.0f / (1.0f + expf(-xo));
            float co = (p == 0) ? cold.x : cold.y;
            float c2 = fmaf(fv, co, iv * gv);
            cn[p] = c2;
            hn[p] = ov * tanhf(c2);
        }
        *reinterpret_cast<float2*>(&out_h[(size_t)row * 1024 + col0]) = make_float2(hn[0], hn[1]);
        *reinterpret_cast<float2*>(&out_c[(size_t)row * 1024 + col0]) = make_float2(cn[0], cn[1]);
    }
}

extern "C" void kernel_launch(void* const* d_in, const int* in_sizes, int n_in,
                              void* d_out, int out_size)
{
    const float* x   = (const float*)d_in[0];
    const float* h_t = (const float*)d_in[1];
    const float* c_t = (const float*)d_in[2];
    const float* w_i = (const float*)d_in[3];
    const float* w_h = (const float*)d_in[4];
    const float* b_i = (const float*)d_in[5];
    const float* b_h = (const float*)d_in[6];
    float* out = (float*)d_out;

    dim3 grid(HDIM / BNJ, MDIM / BM);   // (32, 32)
    dim3 block(256);
    lstm_cell_kernel<<<grid, block>>>(x, h_t, c_t, w_i, w_h, b_i, b_h, out);
}

// round 3
// speedup vs baseline: 2.3647x; 2.3647x over previous
#include <cuda_runtime.h>
#include <cuda_bf16.h>
#include <cstdint>
#include <math.h>

// LSTM cell B=4096, I=1024, H=1024 — bf16 HMMA (mma.sync) path for sm_103 base target.
// ifgo = [x|h] @ [Wi;Wh] + bias via bf16 hi/lo split:
//   fp32 ~= hi+lo  =>  A@W ~= Ahi@Whi + Ahi@Wlo + Alo@Whi   (K' = 3*2048 = 6144)
// CTA tile 256(M) x 128(N) where the 128 N-cols = 32 h-cols x 4 gates interleaved
// (n = jj*4 + g) so the epilogue reads i,f,g,o as one float4 per cell.
// 512 threads, 16 warps (4x4), warp tile 64x32, BK=64, 3-stage cp.async pipeline.

#define MDIM 4096
#define HDIM 1024
#define KD   2048
#define BM   256
#define BN   128
#define TNJ  32
#define BK   64
#define NCHUNK 96                   // 3 passes x 32 chunks of BK=64
#define STAGES 3
#define STAGE_BYTES 49152           // A 256x128B=32KB + B 128x128B=16KB
#define STAGE_B_OFF 32768
#define SMEM_TOTAL (STAGES * STAGE_BYTES)   // 147456

// bf16 hi/lo scratch (64 MB), device globals (sanctioned scratch workaround)
__device__ __align__(16) __nv_bfloat16 g_Ahi[(size_t)MDIM * KD];
__device__ __align__(16) __nv_bfloat16 g_Alo[(size_t)MDIM * KD];
__device__ __align__(16) __nv_bfloat16 g_Whi[(size_t)4096 * KD];   // transposed [n][k]
__device__ __align__(16) __nv_bfloat16 g_Wlo[(size_t)4096 * KD];

__device__ __forceinline__ uint32_t smem_u32(const void* p) {
    uint32_t a;
    asm("{ .reg .u64 t; cvta.to.shared.u64 t, %1; cvt.u32.u64 %0, t; }" : "=r"(a) : "l"(p));
    return a;
}
__device__ __forceinline__ void cp_async16(uint32_t dst, const void* src) {
    asm volatile("cp.async.cg.shared.global [%0], [%1], 16;" :: "r"(dst), "l"(src));
}
#define CP_COMMIT() asm volatile("cp.async.commit_group;" ::: "memory")
#define CP_WAIT1()  asm volatile("cp.async.wait_group 1;" ::: "memory")

__device__ __forceinline__ void ldsm_x4(uint32_t r[4], uint32_t addr) {
    asm volatile("ldmatrix.sync.aligned.m8n8.x4.shared.b16 {%0,%1,%2,%3}, [%4];"
                 : "=r"(r[0]), "=r"(r[1]), "=r"(r[2]), "=r"(r[3]) : "r"(addr));
}
__device__ __forceinline__ void mma_bf16(float d[4], const uint32_t a[4],
                                         uint32_t b0, uint32_t b1) {
    asm volatile(
        "mma.sync.aligned.m16n8k16.row.col.f32.bf16.bf16.f32 "
        "{%0,%1,%2,%3}, {%4,%5,%6,%7}, {%8,%9}, {%0,%1,%2,%3};"
        : "+f"(d[0]), "+f"(d[1]), "+f"(d[2]), "+f"(d[3])
        : "r"(a[0]), "r"(a[1]), "r"(a[2]), "r"(a[3]), "r"(b0), "r"(b1));
}

// ---------------- conversion kernels ----------------
__global__ void conv_A_kernel(const float* __restrict__ x, const float* __restrict__ h) {
    size_t q = (size_t)blockIdx.x * blockDim.x + threadIdx.x;
    int m = (int)(q >> 9);
    int k = ((int)q & 511) << 2;
    const float* src = (k < 1024) ? (x + (size_t)m * 1024 + k)
                                  : (h + (size_t)m * 1024 + (k - 1024));
    float4 v = *reinterpret_cast<const float4*>(src);
    __nv_bfloat16 h0 = __float2bfloat16(v.x), h1 = __float2bfloat16(v.y);
    __nv_bfloat16 h2 = __float2bfloat16(v.z), h3 = __float2bfloat16(v.w);
    __nv_bfloat16 l0 = __float2bfloat16(v.x - __bfloat162float(h0));
    __nv_bfloat16 l1 = __float2bfloat16(v.y - __bfloat162float(h1));
    __nv_bfloat16 l2 = __float2bfloat16(v.z - __bfloat162float(h2));
    __nv_bfloat16 l3 = __float2bfloat16(v.w - __bfloat162float(h3));
    size_t o = (size_t)m * KD + k;
    *reinterpret_cast<__nv_bfloat162*>(&g_Ahi[o])     = __nv_bfloat162(h0, h1);
    *reinterpret_cast<__nv_bfloat162*>(&g_Ahi[o + 2]) = __nv_bfloat162(h2, h3);
    *reinterpret_cast<__nv_bfloat162*>(&g_Alo[o])     = __nv_bfloat162(l0, l1);
    *reinterpret_cast<__nv_bfloat162*>(&g_Alo[o + 2]) = __nv_bfloat162(l2, l3);
}

__global__ void conv_W_kernel(const float* __restrict__ w_i, const float* __restrict__ w_h) {
    __shared__ float tile[32][33];
    int tx = threadIdx.x, ty = threadIdx.y;
    int k0 = blockIdx.x * 32, n0 = blockIdx.y * 32;
    #pragma unroll
    for (int j = 0; j < 4; ++j) {
        int k = k0 + ty + j * 8;
        const float* src = (k < 1024) ? (w_i + (size_t)k * 4096)
                                      : (w_h + (size_t)(k - 1024) * 4096);
        tile[ty + j * 8][tx] = src[n0 + tx];
    }
    __syncthreads();
    #pragma unroll
    for (int j = 0; j < 4; ++j) {
        int n  = n0 + ty + j * 8;
        int kk = k0 + tx;
        float v = tile[tx][ty + j * 8];
        __nv_bfloat16 hi = __float2bfloat16(v);
        __nv_bfloat16 lo = __float2bfloat16(v - __bfloat162float(hi));
        g_Whi[(size_t)n * KD + kk] = hi;
        g_Wlo[(size_t)n * KD + kk] = lo;
    }
}

// ---------------- main GEMM + LSTM kernel ----------------
__global__ __launch_bounds__(512, 1)
void lstm_hmma_kernel(const float* __restrict__ c_t,
                      const float* __restrict__ b_i,
                      const float* __restrict__ b_h,
                      float* __restrict__ out)
{
    extern __shared__ __align__(1024) char dsm[];
    const uint32_t sb = smem_u32(dsm);
    const int tid = threadIdx.x;
    const int wid = tid >> 5;
    const int lid = tid & 31;
    const int mbase = blockIdx.y * BM;
    const int nbase = blockIdx.x * TNJ;

    const int wm = wid & 3;    // 4 row-groups of 64
    const int wn = wid >> 2;   // 4 col-groups of 32

    // ldmatrix per-thread stage-relative offsets (XOR k0b per k-step, see sw128 note)
    uint32_t pa[4], pb[2];
    #pragma unroll
    for (int i = 0; i < 4; ++i) {
        int row  = wm * 64 + i * 16 + (lid & 15);
        int sub  = ((lid >> 4) & 1) * 16;
        pa[i] = row * 128 + (sub ^ ((row & 7) << 4));
    }
    #pragma unroll
    for (int jh = 0; jh < 2; ++jh) {
        int row = wn * 32 + jh * 16 + ((lid >> 4) << 3) + (lid & 7);
        int sub = ((lid >> 3) & 1) * 16;
        pb[jh] = STAGE_B_OFF + row * 128 + (sub ^ ((row & 7) << 4));
    }

    float acc[4][4][4];
    #pragma unroll
    for (int i = 0; i < 4; ++i)
        #pragma unroll
        for (int j = 0; j < 4; ++j)
            #pragma unroll
            for (int c = 0; c < 4; ++c) acc[i][j][c] = 0.0f;

    auto load_stage = [&](int t) {
        const __nv_bfloat16* Asrc; const __nv_bfloat16* Bsrc; int koff;
        if (t < 32)      { Asrc = g_Ahi; Bsrc = g_Whi; koff = t * BK; }
        else if (t < 64) { Asrc = g_Ahi; Bsrc = g_Wlo; koff = (t - 32) * BK; }
        else             { Asrc = g_Alo; Bsrc = g_Whi; koff = (t - 64) * BK; }
        const uint32_t abase = sb + (t % STAGES) * STAGE_BYTES;
        const uint32_t bbase = abase + STAGE_B_OFF;
        #pragma unroll
        for (int q = 0; q < 4; ++q) {            // A: 256 rows x 8 chunks / 512 thr
            int l = q * 512 + tid;
            int row = l >> 3, ck = l & 7;
            uint32_t boff = ck * 16;
            cp_async16(abase + row * 128 + (boff ^ ((row & 7) << 4)),
                       Asrc + (size_t)(mbase + row) * KD + koff + ck * 8);
        }
        #pragma unroll
        for (int q = 0; q < 2; ++q) {            // B: 128 rows x 8 chunks / 512 thr
            int l = q * 512 + tid;
            int r = l >> 3, ck = l & 7;
            int n = ((r & 3) << 10) + nbase + (r >> 2);   // n = g*1024 + nbase + jj
            uint32_t boff = ck * 16;
            cp_async16(bbase + r * 128 + (boff ^ ((r & 7) << 4)),
                       Bsrc + (size_t)n * KD + koff + ck * 8);
        }
    };

    load_stage(0); CP_COMMIT();
    load_stage(1); CP_COMMIT();

    for (int t = 0; t < NCHUNK; ++t) {
        CP_WAIT1();
        __syncthreads();
        if (t + 2 < NCHUNK) load_stage(t + 2);
        CP_COMMIT();

        const uint32_t sbase = sb + (t % STAGES) * STAGE_BYTES;
        #pragma unroll
        for (int ks = 0; ks < 4; ++ks) {
            const uint32_t k0b = ks * 32;
            uint32_t a[4][4], b[2][4];
            #pragma unroll
            for (int i = 0; i < 4; ++i) ldsm_x4(a[i], sbase + (pa[i] ^ k0b));
            #pragma unroll
            for (int jh = 0; jh < 2; ++jh) ldsm_x4(b[jh], sbase + (pb[jh] ^ k0b));
            #pragma unroll
            for (int i = 0; i < 4; ++i) {
                mma_bf16(acc[i][0], a[i], b[0][0], b[0][1]);
                mma_bf16(acc[i][1], a[i], b[0][2], b[0][3]);
                mma_bf16(acc[i][2], a[i], b[1][0], b[1][1]);
                mma_bf16(acc[i][3], a[i], b[1][2], b[1][3]);
            }
        }
    }

    // ---- stage ifgo tile to smem (reuse pipeline smem), then fused LSTM epilogue ----
    __syncthreads();
    float* tile = reinterpret_cast<float*>(dsm);   // [256][132]
    const int trow0 = wm * 64 + (lid >> 2);
    const int tcol0 = wn * 32 + (lid & 3) * 2;
    #pragma unroll
    for (int i = 0; i < 4; ++i)
        #pragma unroll
        for (int j = 0; j < 4; ++j) {
            int r0 = trow0 + i * 16;
            int cc = tcol0 + j * 8;
            *reinterpret_cast<float2*>(&tile[r0 * 132 + cc]) =
                make_float2(acc[i][j][0], acc[i][j][1]);
            *reinterpret_cast<float2*>(&tile[(r0 + 8) * 132 + cc]) =
                make_float2(acc[i][j][2], acc[i][j][3]);
        }
    __syncthreads();

    const int jj = tid & 31;
    const int rg = tid >> 5;
    const int nb = nbase + jj;
    float bias_v[4];
    #pragma unroll
    for (int g = 0; g < 4; ++g)
        bias_v[g] = b_i[g * 1024 + nb] + b_h[g * 1024 + nb];

    float* out_h = out;
    float* out_c = out + (size_t)MDIM * HDIM;
    #pragma unroll
    for (int rr = 0; rr < 16; ++rr) {
        int row  = rg * 16 + rr;
        int grow = mbase + row;
        float4 v = *reinterpret_cast<const float4*>(&tile[row * 132 + jj * 4]);
        float xi = v.x + bias_v[0];
        float xf = v.y + bias_v[1];
        float xg = v.z + bias_v[2];
        float xo = v.w + bias_v[3];
        float iv = 1.0f / (1.0f + __expf(-xi));
        float fv = 1.0f / (1.0f + __expf(-xf));
        float gv = tanhf(xg);
        float ov = 1.0f / (1.0f + __expf(-xo));
        float co = c_t[(size_t)grow * HDIM + nb];
        float c2 = fmaf(fv, co, iv * gv);
        out_c[(size_t)grow * HDIM + nb] = c2;
        out_h[(size_t)grow * HDIM + nb] = ov * tanhf(c2);
    }
}

extern "C" void kernel_launch(void* const* d_in, const int* in_sizes, int n_in,
                              void* d_out, int out_size)
{
    const float* x   = (const float*)d_in[0];
    const float* h_t = (const float*)d_in[1];
    const float* c_t = (const float*)d_in[2];
    const float* w_i = (const float*)d_in[3];
    const float* w_h = (const float*)d_in[4];
    const float* b_i = (const float*)d_in[5];
    const float* b_h = (const float*)d_in[6];
    float* out = (float*)d_out;

    static bool attr_set = false;
    if (!attr_set) {
        cudaFuncSetAttribute(lstm_hmma_kernel,
                             cudaFuncAttributeMaxDynamicSharedMemorySize, SMEM_TOTAL);
        attr_set = true;
    }

    conv_A_kernel<<<8192, 256>>>(x, h_t);
    conv_W_kernel<<<dim3(64, 128), dim3(32, 8)>>>(w_i, w_h);
    lstm_hmma_kernel<<<dim3(HDIM / TNJ, MDIM / BM), 512, SMEM_TOTAL>>>(c_t, b_i, b_h, out);
}

// round 4
// speedup vs baseline: 5.6272x; 2.3796x over previous
#include <cuda_runtime.h>
#include <cuda_fp16.h>
#include <cstdint>
#include <math.h>

// LSTM cell B=4096, I=1024, H=1024 — single-pass fp16 HMMA (mma.sync), fp32 accum.
// ifgo = [x|h] @ [Wi;Wh] + bias, inputs quantized to fp16 (rel err ~2^-11, gated
// output error ~2e-4 << 1e-3 threshold). K = 2048, one GEMM pass.
// CTA tile 256(M) x 128(N); 128 N-cols = 32 h-cols x 4 gates interleaved (n=jj*4+g)
// so the epilogue reads i,f,g,o as one float4. 512 threads, 16 warps (4x4),
// warp tile 64x32, BK=64, 3-stage cp.async pipeline.

#define MDIM 4096
#define HDIM 1024
#define KD   2048
#define BM   256
#define BN   128
#define TNJ  32
#define BK   64
#define NCHUNK 32                   // 2048 / 64
#define STAGES 3
#define STAGE_BYTES 49152           // A 256x128B + B 128x128B
#define STAGE_B_OFF 32768
#define SMEM_TOTAL (STAGES * STAGE_BYTES)   // 147456

// fp16 scratch (32 MB), device globals (sanctioned scratch workaround)
__device__ __align__(16) __half g_Ah[(size_t)MDIM * KD];
__device__ __align__(16) __half g_Wh[(size_t)4096 * KD];   // transposed [n][k]

__device__ __forceinline__ uint32_t smem_u32(const void* p) {
    uint32_t a;
    asm("{ .reg .u64 t; cvta.to.shared.u64 t, %1; cvt.u32.u64 %0, t; }" : "=r"(a) : "l"(p));
    return a;
}
__device__ __forceinline__ void cp_async16(uint32_t dst, const void* src) {
    asm volatile("cp.async.cg.shared.global [%0], [%1], 16;" :: "r"(dst), "l"(src));
}
#define CP_COMMIT() asm volatile("cp.async.commit_group;" ::: "memory")
#define CP_WAIT1()  asm volatile("cp.async.wait_group 1;" ::: "memory")

__device__ __forceinline__ void ldsm_x4(uint32_t r[4], uint32_t addr) {
    asm volatile("ldmatrix.sync.aligned.m8n8.x4.shared.b16 {%0,%1,%2,%3}, [%4];"
                 : "=r"(r[0]), "=r"(r[1]), "=r"(r[2]), "=r"(r[3]) : "r"(addr));
}
__device__ __forceinline__ void mma_fp16(float d[4], const uint32_t a[4],
                                         uint32_t b0, uint32_t b1) {
    asm volatile(
        "mma.sync.aligned.m16n8k16.row.col.f32.f16.f16.f32 "
        "{%0,%1,%2,%3}, {%4,%5,%6,%7}, {%8,%9}, {%0,%1,%2,%3};"
        : "+f"(d[0]), "+f"(d[1]), "+f"(d[2]), "+f"(d[3])
        : "r"(a[0]), "r"(a[1]), "r"(a[2]), "r"(a[3]), "r"(b0), "r"(b1));
}

// ---------------- conversion kernels ----------------
__global__ void conv_A_kernel(const float* __restrict__ x, const float* __restrict__ h) {
    size_t q = (size_t)blockIdx.x * blockDim.x + threadIdx.x;   // 4-elem chunk index
    int m = (int)(q >> 9);
    int k = ((int)q & 511) << 2;
    const float* src = (k < 1024) ? (x + (size_t)m * 1024 + k)
                                  : (h + (size_t)m * 1024 + (k - 1024));
    float4 v = *reinterpret_cast<const float4*>(src);
    size_t o = (size_t)m * KD + k;
    *reinterpret_cast<__half2*>(&g_Ah[o])     = __floats2half2_rn(v.x, v.y);
    *reinterpret_cast<__half2*>(&g_Ah[o + 2]) = __floats2half2_rn(v.z, v.w);
}

__global__ void conv_W_kernel(const float* __restrict__ w_i, const float* __restrict__ w_h) {
    __shared__ float tile[32][33];
    int tx = threadIdx.x, ty = threadIdx.y;
    int k0 = blockIdx.x * 32, n0 = blockIdx.y * 32;
    #pragma unroll
    for (int j = 0; j < 4; ++j) {
        int k = k0 + ty + j * 8;
        const float* src = (k < 1024) ? (w_i + (size_t)k * 4096)
                                      : (w_h + (size_t)(k - 1024) * 4096);
        tile[ty + j * 8][tx] = src[n0 + tx];
    }
    __syncthreads();
    #pragma unroll
    for (int j = 0; j < 4; ++j) {
        int n  = n0 + ty + j * 8;
        int kk = k0 + tx;
        g_Wh[(size_t)n * KD + kk] = __float2half_rn(tile[tx][ty + j * 8]);
    }
}

// ---------------- main GEMM + LSTM kernel ----------------
__global__ __launch_bounds__(512, 1)
void lstm_hmma_kernel(const float* __restrict__ c_t,
                      const float* __restrict__ b_i,
                      const float* __restrict__ b_h,
                      float* __restrict__ out)
{
    extern __shared__ __align__(1024) char dsm[];
    const uint32_t sb = smem_u32(dsm);
    const int tid = threadIdx.x;
    const int wid = tid >> 5;
    const int lid = tid & 31;
    const int mbase = blockIdx.y * BM;
    const int nbase = blockIdx.x * TNJ;

    const int wm = wid & 3;    // 4 row-groups of 64
    const int wn = wid >> 2;   // 4 col-groups of 32

    // ldmatrix per-thread stage-relative offsets (XOR with ks*32 per k-step)
    uint32_t pa[4], pb[2];
    #pragma unroll
    for (int i = 0; i < 4; ++i) {
        int row  = wm * 64 + i * 16 + (lid & 15);
        int sub  = ((lid >> 4) & 1) * 16;
        pa[i] = row * 128 + (sub ^ ((row & 7) << 4));
    }
    #pragma unroll
    for (int jh = 0; jh < 2; ++jh) {
        int row = wn * 32 + jh * 16 + ((lid >> 4) << 3) + (lid & 7);
        int sub = ((lid >> 3) & 1) * 16;
        pb[jh] = STAGE_B_OFF + row * 128 + (sub ^ ((row & 7) << 4));
    }

    float acc[4][4][4];
    #pragma unroll
    for (int i = 0; i < 4; ++i)
        #pragma unroll
        for (int j = 0; j < 4; ++j)
            #pragma unroll
            for (int c = 0; c < 4; ++c) acc[i][j][c] = 0.0f;

    auto load_stage = [&](int t) {
        const int koff = t * BK;
        const uint32_t abase = sb + (t % STAGES) * STAGE_BYTES;
        const uint32_t bbase = abase + STAGE_B_OFF;
        #pragma unroll
        for (int q = 0; q < 4; ++q) {            // A: 256 rows x 8 chunks / 512 thr
            int l = q * 512 + tid;
            int row = l >> 3, ck = l & 7;
            uint32_t boff = ck * 16;
            cp_async16(abase + row * 128 + (boff ^ ((row & 7) << 4)),
                       g_Ah + (size_t)(mbase + row) * KD + koff + ck * 8);
        }
        #pragma unroll
        for (int q = 0; q < 2; ++q) {            // B: 128 rows x 8 chunks / 512 thr
            int l = q * 512 + tid;
            int r = l >> 3, ck = l & 7;
            int n = ((r & 3) << 10) + nbase + (r >> 2);   // n = g*1024 + nbase + jj
            uint32_t boff = ck * 16;
            cp_async16(bbase + r * 128 + (boff ^ ((r & 7) << 4)),
                       g_Wh + (size_t)n * KD + koff + ck * 8);
        }
    };

    load_stage(0); CP_COMMIT();
    load_stage(1); CP_COMMIT();

    for (int t = 0; t < NCHUNK; ++t) {
        CP_WAIT1();
        __syncthreads();
        if (t + 2 < NCHUNK) load_stage(t + 2);
        CP_COMMIT();

        const uint32_t sbase = sb + (t % STAGES) * STAGE_BYTES;
        #pragma unroll
        for (int ks = 0; ks < 4; ++ks) {
            const uint32_t k0b = ks * 32;
            uint32_t a[4][4], b[2][4];
            #pragma unroll
            for (int i = 0; i < 4; ++i) ldsm_x4(a[i], sbase + (pa[i] ^ k0b));
            #pragma unroll
            for (int jh = 0; jh < 2; ++jh) ldsm_x4(b[jh], sbase + (pb[jh] ^ k0b));
            #pragma unroll
            for (int i = 0; i < 4; ++i) {
                mma_fp16(acc[i][0], a[i], b[0][0], b[0][1]);
                mma_fp16(acc[i][1], a[i], b[0][2], b[0][3]);
                mma_fp16(acc[i][2], a[i], b[1][0], b[1][1]);
                mma_fp16(acc[i][3], a[i], b[1][2], b[1][3]);
            }
        }
    }

    // ---- stage ifgo tile to smem (reuse pipeline smem), then fused LSTM epilogue ----
    __syncthreads();
    float* tile = reinterpret_cast<float*>(dsm);   // [256][132]
    const int trow0 = wm * 64 + (lid >> 2);
    const int tcol0 = wn * 32 + (lid & 3) * 2;
    #pragma unroll
    for (int i = 0; i < 4; ++i)
        #pragma unroll
        for (int j = 0; j < 4; ++j) {
            int r0 = trow0 + i * 16;
            int cc = tcol0 + j * 8;
            *reinterpret_cast<float2*>(&tile[r0 * 132 + cc]) =
                make_float2(acc[i][j][0], acc[i][j][1]);
            *reinterpret_cast<float2*>(&tile[(r0 + 8) * 132 + cc]) =
                make_float2(acc[i][j][2], acc[i][j][3]);
        }
    __syncthreads();

    const int jj = tid & 31;
    const int rg = tid >> 5;
    const int nb = nbase + jj;
    float bias_v[4];
    #pragma unroll
    for (int g = 0; g < 4; ++g)
        bias_v[g] = b_i[g * 1024 + nb] + b_h[g * 1024 + nb];

    float* out_h = out;
    float* out_c = out + (size_t)MDIM * HDIM;
    #pragma unroll
    for (int rr = 0; rr < 16; ++rr) {
        int row  = rg * 16 + rr;
        int grow = mbase + row;
        float4 v = *reinterpret_cast<const float4*>(&tile[row * 132 + jj * 4]);
        float xi = v.x + bias_v[0];
        float xf = v.y + bias_v[1];
        float xg = v.z + bias_v[2];
        float xo = v.w + bias_v[3];
        float iv = 1.0f / (1.0f + __expf(-xi));
        float fv = 1.0f / (1.0f + __expf(-xf));
        float gv = tanhf(xg);
        float ov = 1.0f / (1.0f + __expf(-xo));
        float co = c_t[(size_t)grow * HDIM + nb];
        float c2 = fmaf(fv, co, iv * gv);
        out_c[(size_t)grow * HDIM + nb] = c2;
        out_h[(size_t)grow * HDIM + nb] = ov * tanhf(c2);
    }
}

extern "C" void kernel_launch(void* const* d_in, const int* in_sizes, int n_in,
                              void* d_out, int out_size)
{
    const float* x   = (const float*)d_in[0];
    const float* h_t = (const float*)d_in[1];
    const float* c_t = (const float*)d_in[2];
    const float* w_i = (const float*)d_in[3];
    const float* w_h = (const float*)d_in[4];
    const float* b_i = (const float*)d_in[5];
    const float* b_h = (const float*)d_in[6];
    float* out = (float*)d_out;

    static bool attr_set = false;
    if (!attr_set) {
        cudaFuncSetAttribute(lstm_hmma_kernel,
                             cudaFuncAttributeMaxDynamicSharedMemorySize, SMEM_TOTAL);
        attr_set = true;
    }

    conv_A_kernel<<<8192, 256>>>(x, h_t);
    conv_W_kernel<<<dim3(64, 128), dim3(32, 8)>>>(w_i, w_h);
    lstm_hmma_kernel<<<dim3(HDIM / TNJ, MDIM / BM), 512, SMEM_TOTAL>>>(c_t, b_i, b_h, out);
}